// round 1
// baseline (speedup 1.0000x reference)
#include <cuda_runtime.h>
#include <math.h>

// ---------------------------------------------------------------------------
// PermutedNetwork: 6 stages of (offset = conv2d(h)) -> deform_conv2d(h, offset)
// with optional ReLU, then FC(676->256, relu) -> FC(256->10).
// B = 512. Stages (ci, co, k, H_in):
//   1: ( 1,16,3,33)  2: (16,32,3,31)  3: (32,16,5,29)
//   4: (16,16,7,25)  5: (16, 8,5,19)  6: ( 8, 4,3,15)
// ---------------------------------------------------------------------------

#define NTHREADS 256

// Scratch (ping-pong h buffers + offset buffer). Max h = 512*32*29*29 floats,
// max off = 512*98*19*19 floats.
__device__ float g_bufA[13778944];
__device__ float g_bufB[13778944];
__device__ float g_off [18113536];

// ---------------------------------------------------------------------------
// Offset conv: plain VALID conv, NCHW / OIHW. One block per image, input image
// cached in SMEM. Register tile: 2 output channels x 4 pixels.
// ---------------------------------------------------------------------------
template<int CI, int K, int H>
__global__ void __launch_bounds__(NTHREADS) off_conv_k(
    const float* __restrict__ in, const float* __restrict__ ow,
    const float* __restrict__ ob, float* __restrict__ off)
{
    constexpr int W  = H;
    constexpr int Ho = H - K + 1;
    constexpr int P  = Ho * Ho;
    constexpr int HW = H * W;
    constexpr int KK = K * K;
    constexpr int COF = 2 * KK;      // offset channels
    constexpr int OCP = COF / 2;     // oc pairs
    constexpr int PQ  = (P + 3) / 4; // pixel quads

    extern __shared__ float sm[];
    int b = blockIdx.x;
    const float* inb = in + (long)b * CI * HW;
    for (int i = threadIdx.x; i < CI * HW; i += NTHREADS) sm[i] = inb[i];
    __syncthreads();

    float* offb = off + (long)b * COF * P;

    for (int item = threadIdx.x; item < OCP * PQ; item += NTHREADS) {
        int ocp = item / PQ;
        int pq  = item - ocp * PQ;
        int oc0 = ocp * 2;
        int p0  = pq * 4;

        int base[4];
        #pragma unroll
        for (int j = 0; j < 4; j++) {
            int p = min(p0 + j, P - 1);
            int y = p / Ho;
            int x = p - y * Ho;
            base[j] = y * W + x;
        }

        float acc0[4] = {0.f, 0.f, 0.f, 0.f};
        float acc1[4] = {0.f, 0.f, 0.f, 0.f};

        for (int c = 0; c < CI; c++) {
            const float* sc = sm + c * HW;
            const float* w0 = ow + ((long)oc0 * CI + c) * KK;
            const float* w1 = w0 + (long)CI * KK;
            #pragma unroll
            for (int ky = 0; ky < K; ky++) {
                #pragma unroll
                for (int kx = 0; kx < K; kx++) {
                    float wa = __ldg(w0 + ky * K + kx);
                    float wb = __ldg(w1 + ky * K + kx);
                    int o = ky * W + kx;
                    #pragma unroll
                    for (int j = 0; j < 4; j++) {
                        float v = sc[base[j] + o];
                        acc0[j] += wa * v;
                        acc1[j] += wb * v;
                    }
                }
            }
        }
        float bb0 = __ldg(ob + oc0), bb1 = __ldg(ob + oc0 + 1);
        #pragma unroll
        for (int j = 0; j < 4; j++) {
            if (p0 + j < P) {
                offb[(long)oc0 * P + p0 + j]       = acc0[j] + bb0;
                offb[(long)(oc0 + 1) * P + p0 + j] = acc1[j] + bb1;
            }
        }
    }
}

// ---------------------------------------------------------------------------
// Deformable conv. One block per image. Input image + transposed weights in
// SMEM. Each warp handles PIXB pixels at a time: load offsets, compute
// bilinear samples into per-warp SMEM (interleaved by pixel for vector loads),
// then a lane-split (32/CO parts) dot with shfl reduction.
// ---------------------------------------------------------------------------
__device__ __forceinline__ float dsample(const float* ic, int yy, int xx,
                                         int H, int W)
{
    bool v = (yy >= 0) & (yy < H) & (xx >= 0) & (xx < W);
    int yc = min(max(yy, 0), H - 1);
    int xc = min(max(xx, 0), W - 1);
    float val = ic[yc * W + xc];
    return v ? val : 0.f;
}

template<int CI, int CO, int K, int H, int PIXB, bool RELU>
__global__ void __launch_bounds__(NTHREADS) deform_k(
    const float* __restrict__ in, const float* __restrict__ off,
    const float* __restrict__ w, const float* __restrict__ bias,
    float* __restrict__ out)
{
    constexpr int W_  = H;
    constexpr int Ho  = H - K + 1;
    constexpr int P   = Ho * Ho;
    constexpr int HW  = H * W_;
    constexpr int KK  = K * K;
    constexpr int NS  = KK * CI;
    constexpr int COF = 2 * KK;
    constexpr int NW  = NTHREADS / 32;
    constexpr int PARTS = 32 / CO;
    constexpr int T   = (NS + PARTS - 1) / PARTS;
    constexpr int WB  = ((CI * HW + NS * CO + 3) / 4) * 4; // 16B-align warp bufs

    extern __shared__ float sm[];
    float* img = sm;
    float* wT  = sm + CI * HW;
    float* wbase = sm + WB;

    int b = blockIdx.x, tid = threadIdx.x;
    int lane = tid & 31, wid = tid >> 5;

    const float* inb = in + (long)b * CI * HW;
    for (int i = tid; i < CI * HW; i += NTHREADS) img[i] = inb[i];
    // transpose weights: w[oc][c][k] -> wT[(k*CI+c)*CO + oc]
    for (int i = tid; i < CO * NS; i += NTHREADS) {
        int oc = i / NS;
        int r  = i - oc * NS;
        int c  = r / KK;
        int k  = r - c * KK;
        wT[(k * CI + c) * CO + oc] = w[i];
    }
    __syncthreads();

    float* offw = wbase + wid * PIXB * (COF + NS);
    float* sbuf = offw + COF * PIXB;

    int oc   = lane & (CO - 1);
    int part = lane / CO;
    float bval = __ldg(bias + oc);
    const float* offb = off + (long)b * COF * P;

    for (int pc = wid * PIXB; pc < P; pc += NW * PIXB) {
        // load offsets for PIXB pixels, interleaved by pixel
        for (int i = lane; i < COF * PIXB; i += 32) {
            int ch = i / PIXB;
            int p  = i - ch * PIXB;
            int pix = min(pc + p, P - 1);
            offw[i] = offb[ch * P + pix];
        }
        __syncwarp();

        // bilinear samples
        for (int idx = lane; idx < NS * PIXB; idx += 32) {
            int j = idx / PIXB;
            int p = idx - j * PIXB;
            int k = j / CI;
            int c = j - k * CI;
            int pix = min(pc + p, P - 1);
            int yo = pix / Ho;
            int xo = pix - yo * Ho;
            float py = (float)(k / K + yo) + offw[(2 * k) * PIXB + p];
            float px = (float)(k % K + xo) + offw[(2 * k + 1) * PIXB + p];
            float y0f = floorf(py), x0f = floorf(px);
            float wy = py - y0f, wx = px - x0f;
            int y0 = (int)y0f, x0 = (int)x0f;
            const float* ic = img + c * HW;
            float v00 = dsample(ic, y0,     x0,     H, W_);
            float v01 = dsample(ic, y0,     x0 + 1, H, W_);
            float v10 = dsample(ic, y0 + 1, x0,     H, W_);
            float v11 = dsample(ic, y0 + 1, x0 + 1, H, W_);
            float onemwx = 1.f - wx, onemwy = 1.f - wy;
            sbuf[idx] = (v00 * onemwx + v01 * wx) * onemwy
                      + (v10 * onemwx + v11 * wx) * wy;
        }
        __syncwarp();

        // dot: acc[p] = sum_j sbuf[j][p] * wT[j][oc], j split over PARTS lanes
        float acc[PIXB];
        #pragma unroll
        for (int p = 0; p < PIXB; p++) acc[p] = 0.f;

        for (int t = 0; t < T; t++) {
            int j = part + PARTS * t;
            if (PARTS == 1 || j < NS) {
                float wv = wT[j * CO + oc];
                if (PIXB == 4) {
                    float4 sv = *reinterpret_cast<const float4*>(sbuf + j * 4);
                    acc[0] += sv.x * wv;
                    acc[1] += sv.y * wv;
                    acc[2] += sv.z * wv;
                    acc[3 % PIXB] += sv.w * wv; // PIXB==4 here
                } else {
                    float2 sv = *reinterpret_cast<const float2*>(sbuf + j * 2);
                    acc[0] += sv.x * wv;
                    acc[1 % PIXB] += sv.y * wv; // PIXB==2 here
                }
            }
        }

        #pragma unroll
        for (int p = 0; p < PIXB; p++) {
            #pragma unroll
            for (int s = 16; s >= CO; s >>= 1)
                acc[p] += __shfl_down_sync(0xffffffffu, acc[p], s);
        }

        if (lane < CO) {
            #pragma unroll
            for (int p = 0; p < PIXB; p++) {
                if (pc + p < P) {
                    float v = acc[p] + bval;
                    if (RELU) v = fmaxf(v, 0.f);
                    out[((long)b * CO + oc) * P + pc + p] = v;
                }
            }
        }
        __syncwarp();
    }
}

// ---------------------------------------------------------------------------
// Fused FC: relu(flat @ fc1_w^T + b1) @ fc2_w^T + b2. One block per batch row.
// ---------------------------------------------------------------------------
__global__ void __launch_bounds__(NTHREADS) fc_k(
    const float* __restrict__ h, const float* __restrict__ w1,
    const float* __restrict__ b1, const float* __restrict__ w2,
    const float* __restrict__ b2, float* __restrict__ out)
{
    __shared__ float flat[676];
    __shared__ float z[256];
    int b = blockIdx.x, tid = threadIdx.x;
    int lane = tid & 31, wid = tid >> 5;

    for (int i = tid; i < 676; i += NTHREADS) flat[i] = h[(long)b * 676 + i];
    __syncthreads();

    for (int oc = wid; oc < 256; oc += 8) {
        float acc = 0.f;
        const float* wr = w1 + (long)oc * 676;
        for (int i = lane; i < 676; i += 32) acc += flat[i] * wr[i];
        #pragma unroll
        for (int s = 16; s; s >>= 1) acc += __shfl_down_sync(0xffffffffu, acc, s);
        if (lane == 0) z[oc] = fmaxf(acc + b1[oc], 0.f);
    }
    __syncthreads();

    for (int oc = wid; oc < 10; oc += 8) {
        float acc = 0.f;
        const float* wr = w2 + (long)oc * 256;
        for (int i = lane; i < 256; i += 32) acc += z[i] * wr[i];
        #pragma unroll
        for (int s = 16; s; s >>= 1) acc += __shfl_down_sync(0xffffffffu, acc, s);
        if (lane == 0) out[(long)b * 10 + oc] = acc + b2[oc];
    }
}

// ---------------------------------------------------------------------------
// Host side
// ---------------------------------------------------------------------------
template<int CI, int K, int H>
static constexpr int off_smem() { return CI * H * H * 4; }

template<int CI, int CO, int K, int H, int PIXB>
static constexpr int def_smem() {
    constexpr int HW = H * H, KK = K * K, NS = KK * CI, COF = 2 * KK;
    constexpr int WB = ((CI * HW + NS * CO + 3) / 4) * 4;
    return (WB + (NTHREADS / 32) * PIXB * (COF + NS)) * 4;
}

template<int CI, int CO, int K, int H, int PIXB, bool RELU>
static void run_stage(const float* in, const float* ow, const float* ob,
                      const float* w, const float* bias,
                      float* offbuf, float* outbuf)
{
    constexpr int OS = off_smem<CI, K, H>();
    constexpr int DS = def_smem<CI, CO, K, H, PIXB>();
    cudaFuncSetAttribute(off_conv_k<CI, K, H>,
                         cudaFuncAttributeMaxDynamicSharedMemorySize, OS);
    cudaFuncSetAttribute(deform_k<CI, CO, K, H, PIXB, RELU>,
                         cudaFuncAttributeMaxDynamicSharedMemorySize, DS);
    off_conv_k<CI, K, H><<<512, NTHREADS, OS>>>(in, ow, ob, offbuf);
    deform_k<CI, CO, K, H, PIXB, RELU><<<512, NTHREADS, DS>>>(
        in, offbuf, w, bias, outbuf);
}

extern "C" void kernel_launch(void* const* d_in, const int* in_sizes, int n_in,
                              void* d_out, int out_size)
{
    (void)in_sizes; (void)n_in; (void)out_size;
    const float* x = (const float*)d_in[0];
    auto OW = [&](int i) { return (const float*)d_in[4 * i - 3]; };
    auto OB = [&](int i) { return (const float*)d_in[4 * i - 2]; };
    auto WW = [&](int i) { return (const float*)d_in[4 * i - 1]; };
    auto BB = [&](int i) { return (const float*)d_in[4 * i]; };
    const float* fc1w = (const float*)d_in[25];
    const float* fc1b = (const float*)d_in[26];
    const float* fc2w = (const float*)d_in[27];
    const float* fc2b = (const float*)d_in[28];

    float *bufA, *bufB, *off;
    cudaGetSymbolAddress((void**)&bufA, g_bufA);
    cudaGetSymbolAddress((void**)&bufB, g_bufB);
    cudaGetSymbolAddress((void**)&off,  g_off);

    // stage 1: (1 -> 16), K=3, 33 -> 31, relu
    run_stage<1, 16, 3, 33, 4, true >(x,    OW(1), OB(1), WW(1), BB(1), off, bufA);
    // stage 2: (16 -> 32), K=3, 31 -> 29, relu
    run_stage<16, 32, 3, 31, 4, true >(bufA, OW(2), OB(2), WW(2), BB(2), off, bufB);
    // stage 3: (32 -> 16), K=5, 29 -> 25, NO relu
    run_stage<32, 16, 5, 29, 2, false>(bufB, OW(3), OB(3), WW(3), BB(3), off, bufA);
    // stage 4: (16 -> 16), K=7, 25 -> 19, relu
    run_stage<16, 16, 7, 25, 4, true >(bufA, OW(4), OB(4), WW(4), BB(4), off, bufB);
    // stage 5: (16 -> 8),  K=5, 19 -> 15, relu
    run_stage<16, 8, 5, 19, 4, true >(bufB, OW(5), OB(5), WW(5), BB(5), off, bufA);
    // stage 6: (8 -> 4),   K=3, 15 -> 13, relu
    run_stage<8, 4, 3, 15, 4, true >(bufA, OW(6), OB(6), WW(6), BB(6), off, bufB);

    fc_k<<<512, NTHREADS>>>(bufB, fc1w, fc1b, fc2w, fc2b, (float*)d_out);
}

// round 2
// speedup vs baseline: 3.3012x; 3.3012x over previous
#include <cuda_runtime.h>
#include <math.h>

typedef unsigned long long u64;
#define DI __device__ __forceinline__

// ---------------- f32x2 helpers (sm_103a packed math) ----------------
DI u64 pack2(float lo, float hi) {
    u64 r; asm("mov.b64 %0, {%1, %2};" : "=l"(r) : "f"(lo), "f"(hi)); return r;
}
DI void unpack2(u64 v, float& lo, float& hi) {
    asm("mov.b64 {%0, %1}, %2;" : "=f"(lo), "=f"(hi) : "l"(v));
}
DI u64 fma2(u64 a, u64 b, u64 c) {
    u64 d; asm("fma.rn.f32x2 %0, %1, %2, %3;" : "=l"(d) : "l"(a), "l"(b), "l"(c));
    return d;
}

// ---------------- scratch ----------------
__device__ float g_bufA[13778944];
__device__ float g_bufB[13778944];
__device__ float g_off [18113536];
__device__ u64   g_wpk [88064];

// ---------------- weight prepack ----------------
// Offset-conv weights: wpk[ocp*CIKK + r] = (ow[2ocp][r], ow[2ocp+1][r])
__global__ void pack_w_k(const float* __restrict__ ow, u64* __restrict__ dst,
                         int OCP, int CIKK)
{
    int i = blockIdx.x * 256 + threadIdx.x;
    if (i < OCP * CIKK) {
        int ocp = i / CIKK, r = i - ocp * CIKK;
        dst[i] = pack2(ow[(2 * ocp) * CIKK + r], ow[(2 * ocp + 1) * CIKK + r]);
    }
}
// Deform weights transposed: dst[(k*CI+c)*COH + ocp] = (w[2ocp][c][k], w[2ocp+1][c][k])
__global__ void pack_wt_k(const float* __restrict__ w, u64* __restrict__ dst,
                          int COH, int CI, int KK)
{
    int i = blockIdx.x * 256 + threadIdx.x;
    if (i < CI * KK * COH) {
        int j = i / COH, ocp = i - j * COH;
        int k = j / CI, c = j - k * CI;
        dst[i] = pack2(w[((2 * ocp) * CI + c) * KK + k],
                       w[((2 * ocp + 1) * CI + c) * KK + k]);
    }
}

// ---------------- offset conv (plain VALID conv) ----------------
// One block per image, image in SMEM. Thread tile: 2 oc (packed f32x2) x 8
// pixels in one output row, with register row reuse.
template<int CI, int K, int H>
__global__ void __launch_bounds__(256) off_conv_k(
    const float* __restrict__ in, const u64* __restrict__ wpk,
    const float* __restrict__ ob, float* __restrict__ off)
{
    constexpr int W = H, Ho = H - K + 1, Wo = Ho, P = Ho * Wo, HW = H * W;
    constexpr int KK = K * K, OCP = KK;
    constexpr int QW = (Wo + 7) / 8;
    constexpr int ITEMS = OCP * Ho * QW;

    extern __shared__ float img[];
    int b = blockIdx.x;
    {
        const float* inb = in + (long)b * CI * HW;
        for (int i = threadIdx.x; i < CI * HW; i += 256) img[i] = inb[i];
    }
    __syncthreads();

    float* offb = off + (long)b * (2 * KK) * P;

    for (int item = threadIdx.x; item < ITEMS; item += 256) {
        int qx  = item % QW;
        int t   = item / QW;
        int y   = t % Ho;
        int ocp = t / Ho;
        int x0  = qx * 8; if (x0 > Wo - 8) x0 = Wo - 8;

        u64 acc[8];
        u64 bini = pack2(__ldg(ob + 2 * ocp), __ldg(ob + 2 * ocp + 1));
        #pragma unroll
        for (int j = 0; j < 8; j++) acc[j] = bini;

        const u64* wb = wpk + ocp * CI * KK;
        #pragma unroll 1
        for (int c = 0; c < CI; c++) {
            const float* s0 = img + c * HW + y * W + x0;
            const u64* wc = wb + c * KK;
            #pragma unroll
            for (int ky = 0; ky < K; ky++) {
                const float* sr = s0 + ky * W;
                u64 pv[K + 7];
                #pragma unroll
                for (int i = 0; i < K + 7; i++) { float v = sr[i]; pv[i] = pack2(v, v); }
                #pragma unroll
                for (int kx = 0; kx < K; kx++) {
                    u64 wv = __ldg(wc + ky * K + kx);
                    #pragma unroll
                    for (int j = 0; j < 8; j++) acc[j] = fma2(pv[kx + j], wv, acc[j]);
                }
            }
        }
        #pragma unroll
        for (int j = 0; j < 8; j++) {
            float a0, a1; unpack2(acc[j], a0, a1);
            int po = y * Wo + x0 + j;
            offb[(2 * ocp) * P + po]     = a0;
            offb[(2 * ocp + 1) * P + po] = a1;
        }
    }
}

// ---------------- deformable conv ----------------
// One block per image. Image + transposed weight pairs in SMEM. Each thread
// owns PIX strided pixels and ALL output channels (as f32x2 oc-pairs).
// Bilinear corner addresses + validity-masked weights computed once per
// (pixel, k) and reused across all CI channels.
template<int CI, int CO, int K, int H, int PIX, bool RELU>
__global__ void __launch_bounds__(256) deform_k(
    const float* __restrict__ in, const float* __restrict__ off,
    const u64* __restrict__ wt, const float* __restrict__ bias,
    float* __restrict__ out)
{
    constexpr int W = H, Ho = H - K + 1, Wo = Ho, P = Ho * Wo, HW = H * W;
    constexpr int KK = K * K, COH = CO / 2;
    constexpr int NS = KK * CI;
    constexpr int WOFF = (CI * HW + 1) & ~1;   // 8B-align weight area

    extern __shared__ float smf[];
    float* img = smf;
    u64* wts = reinterpret_cast<u64*>(smf + WOFF);

    int b = blockIdx.x, tid = threadIdx.x;
    {
        const float* inb = in + (long)b * CI * HW;
        for (int i = tid; i < CI * HW; i += 256) img[i] = inb[i];
        for (int i = tid; i < NS * COH; i += 256) wts[i] = wt[i];
    }
    __syncthreads();

    const float* offb = off + (long)b * (2 * KK) * P;
    float* outb = out + (long)b * CO * P;

    for (int p0 = tid; p0 < P; p0 += 256 * PIX) {
        int pp[PIX]; bool pval[PIX]; int yo[PIX], xo[PIX];
        #pragma unroll
        for (int i = 0; i < PIX; i++) {
            int p = p0 + i * 256;
            pval[i] = (p < P);
            p = pval[i] ? p : P - 1;
            pp[i] = p;
            yo[i] = p / Wo;
            xo[i] = p - yo[i] * Wo;
        }

        u64 acc[PIX][COH];
        #pragma unroll
        for (int o = 0; o < COH; o++) {
            u64 bini = pack2(__ldg(bias + 2 * o), __ldg(bias + 2 * o + 1));
            #pragma unroll
            for (int i = 0; i < PIX; i++) acc[i][o] = bini;
        }

        #pragma unroll 1
        for (int ky = 0; ky < K; ky++) {
        #pragma unroll 1
        for (int kx = 0; kx < K; kx++) {
            int k = ky * K + kx;
            int a00[PIX], a01[PIX], a10[PIX], a11[PIX];
            float fya[PIX], fyb[PIX], fxa[PIX], fxb[PIX];
            #pragma unroll
            for (int i = 0; i < PIX; i++) {
                float oy = __ldg(offb + (2 * k) * P + pp[i]);
                float ox = __ldg(offb + (2 * k + 1) * P + pp[i]);
                float py = (float)(ky + yo[i]) + oy;
                float px = (float)(kx + xo[i]) + ox;
                float y0f = floorf(py), x0f = floorf(px);
                float wy = py - y0f, wx = px - x0f;
                int y0 = (int)y0f, x0 = (int)x0f;
                fya[i] = (y0 >= 0 && y0 < H)          ? (1.f - wy) : 0.f;
                fyb[i] = (y0 >= -1 && y0 < H - 1)     ? wy : 0.f;
                fxa[i] = (x0 >= 0 && x0 < W)          ? (1.f - wx) : 0.f;
                fxb[i] = (x0 >= -1 && x0 < W - 1)     ? wx : 0.f;
                int y0c = min(max(y0, 0), H - 1);
                int y1c = min(max(y0 + 1, 0), H - 1);
                int x0c = min(max(x0, 0), W - 1);
                int x1c = min(max(x0 + 1, 0), W - 1);
                a00[i] = y0c * W + x0c; a01[i] = y0c * W + x1c;
                a10[i] = y1c * W + x0c; a11[i] = y1c * W + x1c;
            }
            const u64* wrow = wts + k * CI * COH;
            #pragma unroll 2
            for (int c = 0; c < CI; c++) {
                const float* ic = img + c * HW;
                u64 ss[PIX];
                #pragma unroll
                for (int i = 0; i < PIX; i++) {
                    float t0 = ic[a00[i]] * fxa[i] + ic[a01[i]] * fxb[i];
                    float t1 = ic[a10[i]] * fxa[i] + ic[a11[i]] * fxb[i];
                    float s  = t0 * fya[i] + t1 * fyb[i];
                    ss[i] = pack2(s, s);
                }
                const u64* wc = wrow + c * COH;
                #pragma unroll
                for (int o = 0; o < COH; o++) {
                    u64 wv = wc[o];
                    #pragma unroll
                    for (int i = 0; i < PIX; i++) acc[i][o] = fma2(ss[i], wv, acc[i][o]);
                }
            }
        }}

        #pragma unroll
        for (int i = 0; i < PIX; i++) if (pval[i]) {
            #pragma unroll
            for (int o = 0; o < COH; o++) {
                float a0, a1; unpack2(acc[i][o], a0, a1);
                if (RELU) { a0 = fmaxf(a0, 0.f); a1 = fmaxf(a1, 0.f); }
                outb[(2 * o) * P + pp[i]]     = a0;
                outb[(2 * o + 1) * P + pp[i]] = a1;
            }
        }
    }
}

// ---------------- fused FC ----------------
__global__ void __launch_bounds__(256) fc_k(
    const float* __restrict__ h, const float* __restrict__ w1,
    const float* __restrict__ b1, const float* __restrict__ w2,
    const float* __restrict__ b2, float* __restrict__ out)
{
    __shared__ float flat[676];
    __shared__ float z[256];
    int b = blockIdx.x, tid = threadIdx.x;
    int lane = tid & 31, wid = tid >> 5;

    for (int i = tid; i < 676; i += 256) flat[i] = h[(long)b * 676 + i];
    __syncthreads();

    for (int oc = wid; oc < 256; oc += 8) {
        float acc = 0.f;
        const float* wr = w1 + (long)oc * 676;
        for (int i = lane; i < 676; i += 32) acc += flat[i] * wr[i];
        #pragma unroll
        for (int s = 16; s; s >>= 1) acc += __shfl_down_sync(0xffffffffu, acc, s);
        if (lane == 0) z[oc] = fmaxf(acc + b1[oc], 0.f);
    }
    __syncthreads();

    for (int oc = wid; oc < 10; oc += 8) {
        float acc = 0.f;
        const float* wr = w2 + (long)oc * 256;
        for (int i = lane; i < 256; i += 32) acc += z[i] * wr[i];
        #pragma unroll
        for (int s = 16; s; s >>= 1) acc += __shfl_down_sync(0xffffffffu, acc, s);
        if (lane == 0) out[(long)b * 10 + oc] = acc + b2[oc];
    }
}

// ---------------- host ----------------
template<int CI, int K, int H>
static void launch_off(const float* in, const u64* wpk, const float* ob, float* off)
{
    constexpr int SM = CI * H * H * 4;
    cudaFuncSetAttribute(off_conv_k<CI, K, H>,
                         cudaFuncAttributeMaxDynamicSharedMemorySize, SM);
    off_conv_k<CI, K, H><<<512, 256, SM>>>(in, wpk, ob, off);
}

template<int CI, int CO, int K, int H, int PIX, bool RELU>
static void launch_def(const float* in, const float* off, const u64* wt,
                       const float* bias, float* out)
{
    constexpr int WOFF = (CI * H * H + 1) & ~1;
    constexpr int SM = WOFF * 4 + K * K * CI * (CO / 2) * 8;
    cudaFuncSetAttribute(deform_k<CI, CO, K, H, PIX, RELU>,
                         cudaFuncAttributeMaxDynamicSharedMemorySize, SM);
    deform_k<CI, CO, K, H, PIX, RELU><<<512, 256, SM>>>(in, off, wt, bias, out);
}

extern "C" void kernel_launch(void* const* d_in, const int* in_sizes, int n_in,
                              void* d_out, int out_size)
{
    (void)in_sizes; (void)n_in; (void)out_size;
    const float* x = (const float*)d_in[0];
    auto OW = [&](int i) { return (const float*)d_in[4 * i - 3]; };
    auto OB = [&](int i) { return (const float*)d_in[4 * i - 2]; };
    auto WW = [&](int i) { return (const float*)d_in[4 * i - 1]; };
    auto BB = [&](int i) { return (const float*)d_in[4 * i]; };
    const float* fc1w = (const float*)d_in[25];
    const float* fc1b = (const float*)d_in[26];
    const float* fc2w = (const float*)d_in[27];
    const float* fc2b = (const float*)d_in[28];

    float *bufA, *bufB, *off;
    u64* wpk;
    cudaGetSymbolAddress((void**)&bufA, g_bufA);
    cudaGetSymbolAddress((void**)&bufB, g_bufB);
    cudaGetSymbolAddress((void**)&off,  g_off);
    cudaGetSymbolAddress((void**)&wpk,  g_wpk);

    // wpk layout (u64 offsets)
    // off-conv packs:
    const int O1 = 0, O2 = 81, O3 = 1377, O4 = 21377, O5 = 59793, O6 = 69793;
    // deform packs:
    const int D1 = 70441, D2 = 70513, D3 = 72817, D4 = 79217, D5 = 85489, D6 = 87089;

    auto gp = [](int n) { return (n + 255) / 256; };
    // stage params: (OCP, CIKK) for off-conv; (COH, CI, KK) for deform
    pack_w_k <<<gp(   81), 256>>>(OW(1), wpk + O1,  9,   9);
    pack_w_k <<<gp( 1296), 256>>>(OW(2), wpk + O2,  9, 144);
    pack_w_k <<<gp(20000), 256>>>(OW(3), wpk + O3, 25, 800);
    pack_w_k <<<gp(38416), 256>>>(OW(4), wpk + O4, 49, 784);
    pack_w_k <<<gp(10000), 256>>>(OW(5), wpk + O5, 25, 400);
    pack_w_k <<<gp(  648), 256>>>(OW(6), wpk + O6,  9,  72);
    pack_wt_k<<<gp(   72), 256>>>(WW(1), wpk + D1,  8,  1,  9);
    pack_wt_k<<<gp( 2304), 256>>>(WW(2), wpk + D2, 16, 16,  9);
    pack_wt_k<<<gp( 6400), 256>>>(WW(3), wpk + D3,  8, 32, 25);
    pack_wt_k<<<gp( 6272), 256>>>(WW(4), wpk + D4,  8, 16, 49);
    pack_wt_k<<<gp( 1600), 256>>>(WW(5), wpk + D5,  4, 16, 25);
    pack_wt_k<<<gp(  144), 256>>>(WW(6), wpk + D6,  2,  8,  9);

    // stage 1: (1 -> 16), K=3, 33 -> 31, relu
    launch_off<1, 3, 33>(x, wpk + O1, OB(1), off);
    launch_def<1, 16, 3, 33, 4, true>(x, off, wpk + D1, BB(1), bufA);
    // stage 2: (16 -> 32), K=3, 31 -> 29, relu
    launch_off<16, 3, 31>(bufA, wpk + O2, OB(2), off);
    launch_def<16, 32, 3, 31, 2, true>(bufA, off, wpk + D2, BB(2), bufB);
    // stage 3: (32 -> 16), K=5, 29 -> 25, no relu
    launch_off<32, 5, 29>(bufB, wpk + O3, OB(3), off);
    launch_def<32, 16, 5, 29, 2, false>(bufB, off, wpk + D3, BB(3), bufA);
    // stage 4: (16 -> 16), K=7, 25 -> 19, relu
    launch_off<16, 7, 25>(bufA, wpk + O4, OB(4), off);
    launch_def<16, 16, 7, 25, 2, true>(bufA, off, wpk + D4, BB(4), bufB);
    // stage 5: (16 -> 8), K=5, 19 -> 15, relu
    launch_off<16, 5, 19>(bufB, wpk + O5, OB(5), off);
    launch_def<16, 8, 5, 19, 1, true>(bufB, off, wpk + D5, BB(5), bufA);
    // stage 6: (8 -> 4), K=3, 15 -> 13, relu
    launch_off<8, 3, 15>(bufA, wpk + O6, OB(6), off);
    launch_def<8, 4, 3, 15, 1, true>(bufA, off, wpk + D6, BB(6), bufB);

    fc_k<<<512, 256>>>(bufB, fc1w, fc1b, fc2w, fc2b, (float*)d_out);
}